// round 15
// baseline (speedup 1.0000x reference)
#include <cuda_runtime.h>
#include <math.h>

#define B_    64
#define S_    512
#define EMB_  512
#define HID_  1024
#define NCTA  128
#define NC    8          // output columns per CTA
#define TPB   512        // 16 warps; warp kg owns k-rows [kg*64, kg*64+64)
#define NW    16

// SMEM floats: 3 plain weight arrays (3*8192) + reduction scratch (16384) = 40960 floats
#define WSZ        8192          // floats per weight array [HID_][NC]
#define RED_OFF    24576
#define SMEM_BYTES (40960 * 4)   // 163840 B -> 1 CTA/SM

// -------- scratch (static device globals; no allocation) --------
__device__ float g_pre1[(size_t)S_ * HID_ * B_];   // [t][n][b]
__device__ float g_H1[2][HID_ * B_];               // [parity][k][m]
__device__ float g_H2[2][HID_ * B_];
__device__ unsigned g_cnt;
__device__ unsigned g_gen;

// -------- grid barrier (proven R6/R8/R9/R10/R13): atomic count + acquire/release gen ----
__device__ __forceinline__ unsigned ld_acq(const unsigned* p) {
    unsigned v;
    asm volatile("ld.acquire.gpu.u32 %0, [%1];" : "=r"(v) : "l"(p) : "memory");
    return v;
}
__device__ __forceinline__ void grid_barrier() {
    __syncthreads();
    if (threadIdx.x == 0) {
        __threadfence();
        unsigned my = ld_acq(&g_gen);
        if (atomicAdd(&g_cnt, 1u) == NCTA - 1) {
            atomicExch(&g_cnt, 0u);
            asm volatile("st.release.gpu.u32 [%0], %1;" :: "l"(&g_gen), "r"(my + 1) : "memory");
        } else {
            while (ld_acq(&g_gen) == my) { __nanosleep(24); }
        }
    }
    __syncthreads();
}

// packed fp32x2 FMA
__device__ __forceinline__ void ffma2(unsigned long long& a,
                                      unsigned long long x,
                                      unsigned long long w) {
    asm("fma.rn.f32x2 %0, %1, %2, %0;" : "+l"(a) : "l"(x), "l"(w));
}
__device__ __forceinline__ unsigned long long dup2(float w) {
    unsigned u = __float_as_uint(w);
    unsigned long long r;
    asm("mov.b64 %0, {%1, %1};" : "=l"(r) : "r"(u));
    return r;
}
struct u64x2 { unsigned long long x, y; };
__device__ __forceinline__ u64x2 ldcg16(const float* p) {
    double2 v = __ldcg((const double2*)p);
    u64x2 r;
    r.x = (unsigned long long)__double_as_longlong(v.x);
    r.y = (unsigned long long)__double_as_longlong(v.y);
    return r;
}
__device__ __forceinline__ float2 unpack2(unsigned long long a) {
    float2 f;
    asm("mov.b64 {%0, %1}, %2;" : "=f"(f.x), "=f"(f.y) : "l"(a));
    return f;
}

// ================= precompute: pre1[t][n][b] = emb[x[b][t]] @ Wi1 + b1 =================
// FFMA2 version: As staged as duplicated {a,a} u64 pairs (row stride 66 u64 -> 16B
// aligned, odd stride avoids systematic conflicts), Bs read as natural u64 n-pairs.
// Inner loop per k: 3 LDS.128 + 8 FFMA2 (was 2 LDS.128 + 16 FFMA). No cross-CTA sync.
__global__ __launch_bounds__(256) void pre_kernel(
    const int* __restrict__ x, const float* __restrict__ emb,
    const float* __restrict__ Wi1, const float* __restrict__ b1)
{
    __shared__ int tok[64];
    __shared__ unsigned long long As2[32 * 66];   // [k][b] {a,a}
    __shared__ float Bs[32 * 64];                 // [k][n]
    const int tid = threadIdx.x;
    const int t   = blockIdx.y;
    const int n0  = blockIdx.x * 64;

    if (tid < 64) tok[tid] = x[tid * S_ + t];
    __syncthreads();

    const int ty = tid >> 4, tx = tid & 15;       // ty: b-quad, tx: n-quad
    unsigned long long acc[4][2];                 // [b elem][n-pair]
    #pragma unroll
    for (int bi = 0; bi < 4; ++bi) { acc[bi][0] = 0ull; acc[bi][1] = 0ull; }

    const int b_l = tid >> 2, kq = tid & 3;
    for (int kt = 0; kt < 16; ++kt) {
        __syncthreads();
        #pragma unroll
        for (int j = 0; j < 2; ++j) {
            int k4 = kq * 4 + j * 16;
            float4 v = *(const float4*)&emb[(size_t)tok[b_l] * EMB_ + kt * 32 + k4];
            As2[(k4+0)*66 + b_l] = dup2(v.x);
            As2[(k4+1)*66 + b_l] = dup2(v.y);
            As2[(k4+2)*66 + b_l] = dup2(v.z);
            As2[(k4+3)*66 + b_l] = dup2(v.w);
        }
        #pragma unroll
        for (int j = 0; j < 2; ++j) {
            int kl = (tid >> 4) + j * 16;
            int nq = tid & 15;
            *(float4*)&Bs[kl*64 + nq*4] =
                *(const float4*)&Wi1[(size_t)(kt*32 + kl) * HID_ + n0 + nq*4];
        }
        __syncthreads();
        #pragma unroll
        for (int k = 0; k < 32; ++k) {
            const unsigned long long* ar = &As2[k*66 + ty*4];
            ulonglong2 a01 = *(const ulonglong2*)&ar[0];            // LDS.128
            ulonglong2 a23 = *(const ulonglong2*)&ar[2];            // LDS.128
            ulonglong2 bp  = *(const ulonglong2*)&Bs[k*64 + tx*4];  // LDS.128
            ffma2(acc[0][0], a01.x, bp.x); ffma2(acc[0][1], a01.x, bp.y);
            ffma2(acc[1][0], a01.y, bp.x); ffma2(acc[1][1], a01.y, bp.y);
            ffma2(acc[2][0], a23.x, bp.x); ffma2(acc[2][1], a23.x, bp.y);
            ffma2(acc[3][0], a23.y, bp.x); ffma2(acc[3][1], a23.y, bp.y);
        }
    }

    float4 b1v = *(const float4*)&b1[n0 + tx*4];
    float fc[4][4];
    #pragma unroll
    for (int bi = 0; bi < 4; ++bi) {
        float2 lo = unpack2(acc[bi][0]);
        float2 hi = unpack2(acc[bi][1]);
        fc[bi][0] = lo.x + b1v.x;
        fc[bi][1] = lo.y + b1v.y;
        fc[bi][2] = hi.x + b1v.z;
        fc[bi][3] = hi.y + b1v.w;
    }
    float* outp = &g_pre1[(size_t)t * (HID_*B_)];
    #pragma unroll
    for (int ni = 0; ni < 4; ++ni) {
        float4 c = make_float4(fc[0][ni], fc[1][ni], fc[2][ni], fc[3][ni]);
        *(float4*)&outp[(n0 + tx*4 + ni)*B_ + ty*4] = c;
    }
}

// ================= persistent recurrent kernel (byte-identical to R13 pass) ==========
// 16 warps. Warp kg owns k-rows [kg*64, kg*64+64). Lane (cp,q): cols c0..c0+3,
// batch rows m4..m4+3. h read from L2 (ldcg); weights plain [k][8] in smem.
// Conflict-free partials; distributed finalize.
__global__ void __launch_bounds__(TPB, 1) recur_kernel(
    const float* __restrict__ Wh1, const float* __restrict__ Wi2,
    const float* __restrict__ Wh2, const float* __restrict__ b2,
    const float* __restrict__ Wd,  const float* __restrict__ bd,
    float* __restrict__ out)
{
    extern __shared__ float sm[];
    float* Ws1  = sm;                 // [HID_][8]
    float* Wsi  = sm + WSZ;
    float* Ws2  = sm + 2 * WSZ;
    float* redA = sm + RED_OFF;       // 8192 floats (h1 partials)
    float* redB = sm + RED_OFF + 8192;// 8192 floats (h2 partials)

    const int tid  = threadIdx.x;
    const int c    = blockIdx.x;
    const int kg   = tid >> 5;           // warp = k-group 0..15
    const int lane = tid & 31;
    const int cp   = lane >> 4;          // col-quad 0..1
    const int q    = lane & 15;          // m-quad 0..15
    const int m4   = q * 4;
    const int c0   = c * NC + cp * 4;

    // fill plain weight slices [k][8]
    for (int k = tid; k < HID_; k += TPB) {
        #pragma unroll
        for (int hh = 0; hh < 2; ++hh) {
            int h4 = hh * 4;
            int col = c * NC + h4;
            float4 v;
            v.x = Wh1[(size_t)k * HID_ + col];     v.y = Wh1[(size_t)k * HID_ + col + 1];
            v.z = Wh1[(size_t)k * HID_ + col + 2]; v.w = Wh1[(size_t)k * HID_ + col + 3];
            *(float4*)&Ws1[k * 8 + h4] = v;
            v.x = Wi2[(size_t)k * HID_ + col];     v.y = Wi2[(size_t)k * HID_ + col + 1];
            v.z = Wi2[(size_t)k * HID_ + col + 2]; v.w = Wi2[(size_t)k * HID_ + col + 3];
            *(float4*)&Wsi[k * 8 + h4] = v;
            v.x = Wh2[(size_t)k * HID_ + col];     v.y = Wh2[(size_t)k * HID_ + col + 1];
            v.z = Wh2[(size_t)k * HID_ + col + 2]; v.w = Wh2[(size_t)k * HID_ + col + 3];
            *(float4*)&Ws2[k * 8 + h4] = v;
        }
    }
    if (tid < 128) {
        float4 z = {0,0,0,0};
        *(float4*)&g_H1[0][c * NC * B_ + tid * 4] = z;
        *(float4*)&g_H2[0][c * NC * B_ + tid * 4] = z;
    }
    // scalar b2 for h2-reducing warps (kg 4..7): col = c*NC + cp*4 + (kg-4)
    const float b2s = b2[c * NC + cp * 4 + (kg & 3)];
    grid_barrier();

    for (int p = 0; p <= S_; ++p) {
        const int pr = p & 1;
        const float* H1r = g_H1[pr] + (kg << 6) * B_ + m4;    // h1(p), warp k-slice
        const float* H2r = g_H2[pr ^ 1] + (kg << 6) * B_ + m4;

        unsigned long long a1[4][2], a2[4][2];
        #pragma unroll
        for (int ci = 0; ci < 4; ++ci) {
            a1[ci][0] = a1[ci][1] = 0ull;
            a2[ci][0] = a2[ci][1] = 0ull;
        }
        if (kg == 0 && p < S_) {         // seed a1 with pre1 (this thread's tile)
            const float* pp = &g_pre1[(size_t)p * (HID_ * B_)];
            #pragma unroll
            for (int ci = 0; ci < 4; ++ci) {
                ulonglong2 v = *(const ulonglong2*)&pp[(c0 + ci) * B_ + m4];
                a1[ci][0] = v.x; a1[ci][1] = v.y;
            }
        }

        const float* w1p = Ws1 + (kg << 6) * 8 + cp * 4;
        const float* wip = Wsi + (kg << 6) * 8 + cp * 4;
        const float* w2p = Ws2 + (kg << 6) * 8 + cp * 4;

        #pragma unroll 8
        for (int kk = 0; kk < 64; ++kk) {
            u64x2 h1 = ldcg16(H1r + kk * B_);
            u64x2 h2 = ldcg16(H2r + kk * B_);
            float4 w1 = *(const float4*)&w1p[kk * 8];
            float4 wi = *(const float4*)&wip[kk * 8];
            float4 w2 = *(const float4*)&w2p[kk * 8];
            const float w1a[4] = {w1.x, w1.y, w1.z, w1.w};
            const float wia[4] = {wi.x, wi.y, wi.z, wi.w};
            const float w2a[4] = {w2.x, w2.y, w2.z, w2.w};
            #pragma unroll
            for (int ci = 0; ci < 4; ++ci) {
                unsigned long long w1d = dup2(w1a[ci]);
                unsigned long long wid = dup2(wia[ci]);
                unsigned long long w2d = dup2(w2a[ci]);
                ffma2(a1[ci][0], h1.x, w1d);
                ffma2(a1[ci][1], h1.y, w1d);
                ffma2(a2[ci][0], h1.x, wid);
                ffma2(a2[ci][1], h1.y, wid);
                ffma2(a2[ci][0], h2.x, w2d);
                ffma2(a2[ci][1], h2.y, w2d);
            }
        }

        // partials -> smem, conflict-free layout:
        //   component j of (kg,lane): redA/redB[((j*16+kg)*32+lane)*4]
        {
            #pragma unroll
            for (int j = 0; j < 4; ++j) {
                ulonglong2 u;
                u.x = a1[j][0]; u.y = a1[j][1];
                *(ulonglong2*)&redA[((j * 16 + kg) * 32 + lane) * 4] = u;
            }
            #pragma unroll
            for (int j = 0; j < 4; ++j) {
                ulonglong2 u;
                u.x = a2[j][0]; u.y = a2[j][1];
                *(ulonglong2*)&redB[((j * 16 + kg) * 32 + lane) * 4] = u;
            }
        }
        __syncthreads();

        // distributed finalize (conflict-free reads): warp j -> h1 col j; warp 4+j -> h2.
        if (kg < 4 && p < S_) {
            const int j = kg;
            float4 f = {0, 0, 0, 0};
            #pragma unroll
            for (int g = 0; g < NW; ++g) {
                float4 v = *(const float4*)&redA[((j * 16 + g) * 32 + lane) * 4];
                f.x += v.x; f.y += v.y; f.z += v.z; f.w += v.w;
            }
            float4 o = make_float4(tanhf(f.x), tanhf(f.y), tanhf(f.z), tanhf(f.w));
            *(float4*)&g_H1[pr ^ 1][(c0 + j) * B_ + m4] = o;
        }
        if (kg >= 4 && kg < 8 && p > 0) {
            const int j = kg - 4;
            float4 f = {b2s, b2s, b2s, b2s};
            #pragma unroll
            for (int g = 0; g < NW; ++g) {
                float4 v = *(const float4*)&redB[((j * 16 + g) * 32 + lane) * 4];
                f.x += v.x; f.y += v.y; f.z += v.z; f.w += v.w;
            }
            float4 o = make_float4(tanhf(f.x), tanhf(f.y), tanhf(f.z), tanhf(f.w));
            *(float4*)&g_H2[pr][(c0 + j) * B_ + m4] = o;
        }
        grid_barrier();
    }

    // epilogue: out[b] = sigmoid(h2(512) @ Wd + bd); h2(512) at parity 0
    if (c == 0 && tid < 128) {
        const int b = tid >> 1, h = tid & 1;
        const float* H2f = g_H2[0];
        float s = 0.f;
        #pragma unroll 8
        for (int k = h * 512; k < h * 512 + 512; ++k)
            s += __ldcg(&H2f[k * B_ + b]) * Wd[k];
        s += __shfl_xor_sync(0xffffffffu, s, 1);
        if (h == 0) out[b] = 1.f / (1.f + expf(-(s + bd[0])));
    }
}

// ================= launch =================
extern "C" void kernel_launch(void* const* d_in, const int* in_sizes, int n_in,
                              void* d_out, int out_size) {
    const int*   x   = (const int*)  d_in[0];
    const float* emb = (const float*)d_in[1];
    const float* Wi1 = (const float*)d_in[2];
    const float* Wh1 = (const float*)d_in[3];
    const float* b1  = (const float*)d_in[4];
    const float* Wi2 = (const float*)d_in[5];
    const float* Wh2 = (const float*)d_in[6];
    const float* b2  = (const float*)d_in[7];
    const float* Wd  = (const float*)d_in[8];
    const float* bd  = (const float*)d_in[9];
    float* out = (float*)d_out;

    cudaFuncSetAttribute(recur_kernel,
                         cudaFuncAttributeMaxDynamicSharedMemorySize, SMEM_BYTES);

    pre_kernel<<<dim3(16, 512), 256>>>(x, emb, Wi1, b1);
    recur_kernel<<<NCTA, TPB, SMEM_BYTES>>>(Wh1, Wi2, Wh2, b2, Wd, bd, out);
}

// round 17
// speedup vs baseline: 1.0298x; 1.0298x over previous
#include <cuda_runtime.h>
#include <math.h>

#define B_    64
#define S_    512
#define EMB_  512
#define HID_  1024
#define NCTA  128
#define NC    8          // output columns per CTA
#define TPB   512        // 16 warps; warp kg owns k-rows [kg*64, kg*64+64)
#define NW    16

// SMEM floats: 3 plain weight arrays (3*8192) + reduction scratch (16384) = 40960 floats
#define WSZ        8192          // floats per weight array [HID_][NC]
#define RED_OFF    24576
#define SMEM_BYTES (40960 * 4)   // 163840 B -> 1 CTA/SM

// -------- scratch (static device globals; no allocation) --------
__device__ float g_pre1[(size_t)S_ * HID_ * B_];   // [t][n][b]
__device__ float g_H1[2][HID_ * B_];               // [parity][k][m]
__device__ float g_H2[2][HID_ * B_];
__device__ unsigned g_cnt;
__device__ unsigned g_gen;

// -------- grid barrier (proven R6/R8/R9/R10/R13): atomic count + acquire/release gen ----
__device__ __forceinline__ unsigned ld_acq(const unsigned* p) {
    unsigned v;
    asm volatile("ld.acquire.gpu.u32 %0, [%1];" : "=r"(v) : "l"(p) : "memory");
    return v;
}
__device__ __forceinline__ void grid_barrier() {
    __syncthreads();
    if (threadIdx.x == 0) {
        __threadfence();
        unsigned my = ld_acq(&g_gen);
        if (atomicAdd(&g_cnt, 1u) == NCTA - 1) {
            atomicExch(&g_cnt, 0u);
            asm volatile("st.release.gpu.u32 [%0], %1;" :: "l"(&g_gen), "r"(my + 1) : "memory");
        } else {
            while (ld_acq(&g_gen) == my) { __nanosleep(24); }
        }
    }
    __syncthreads();
}

// packed fp32x2 FMA
__device__ __forceinline__ void ffma2(unsigned long long& a,
                                      unsigned long long x,
                                      unsigned long long w) {
    asm("fma.rn.f32x2 %0, %1, %2, %0;" : "+l"(a) : "l"(x), "l"(w));
}
__device__ __forceinline__ unsigned long long dup2(float w) {
    unsigned u = __float_as_uint(w);
    unsigned long long r;
    asm("mov.b64 %0, {%1, %1};" : "=l"(r) : "r"(u));
    return r;
}
struct u64x2 { unsigned long long x, y; };
__device__ __forceinline__ u64x2 ldcg16(const float* p) {
    double2 v = __ldcg((const double2*)p);
    u64x2 r;
    r.x = (unsigned long long)__double_as_longlong(v.x);
    r.y = (unsigned long long)__double_as_longlong(v.y);
    return r;
}
__device__ __forceinline__ float2 unpack2(unsigned long long a) {
    float2 f;
    asm("mov.b64 {%0, %1}, %2;" : "=f"(f.x), "=f"(f.y) : "l"(a));
    return f;
}

// ================= precompute: pre1[t][n][b] = emb[x[b][t]] @ Wi1 + b1 =================
// FFMA2 with IN-REGISTER duplication: SMEM layouts identical to R13 (As [k][b] pad 68,
// Bs [k][n]). Inner k-step: 2 LDS.128 + 4 dup2 (ALU) + 8 FFMA2 (was 2 LDS + 16 FFMA).
// Per-output accumulation order identical to R13. No cross-CTA sync anywhere.
__global__ __launch_bounds__(256) void pre_kernel(
    const int* __restrict__ x, const float* __restrict__ emb,
    const float* __restrict__ Wi1, const float* __restrict__ b1)
{
    __shared__ int   tok[64];
    __shared__ float As[32 * 68];
    __shared__ float Bs[32 * 64];
    const int tid = threadIdx.x;
    const int t   = blockIdx.y;
    const int n0  = blockIdx.x * 64;

    if (tid < 64) tok[tid] = x[tid * S_ + t];
    __syncthreads();

    const int ty = tid >> 4, tx = tid & 15;       // ty: b-quad, tx: n-quad
    unsigned long long acc[4][2];                 // [b elem][n-pair {2j,2j+1}]
    #pragma unroll
    for (int bi = 0; bi < 4; ++bi) { acc[bi][0] = 0ull; acc[bi][1] = 0ull; }

    const int b_l = tid >> 2, kq = tid & 3;
    for (int kt = 0; kt < 16; ++kt) {
        __syncthreads();
        #pragma unroll
        for (int j = 0; j < 2; ++j) {
            int k4 = kq * 4 + j * 16;
            float4 v = *(const float4*)&emb[(size_t)tok[b_l] * EMB_ + kt * 32 + k4];
            As[(k4+0)*68 + b_l] = v.x;
            As[(k4+1)*68 + b_l] = v.y;
            As[(k4+2)*68 + b_l] = v.z;
            As[(k4+3)*68 + b_l] = v.w;
        }
        #pragma unroll
        for (int j = 0; j < 2; ++j) {
            int kl = (tid >> 4) + j * 16;
            int nq = tid & 15;
            *(float4*)&Bs[kl*64 + nq*4] =
                *(const float4*)&Wi1[(size_t)(kt*32 + kl) * HID_ + n0 + nq*4];
        }
        __syncthreads();
        #pragma unroll
        for (int k = 0; k < 32; ++k) {
            float4 av = *(const float4*)&As[k*68 + ty*4];                 // LDS.128
            ulonglong2 bp = *(const ulonglong2*)&Bs[k*64 + tx*4];        // LDS.128
            unsigned long long a0 = dup2(av.x);
            unsigned long long a1 = dup2(av.y);
            unsigned long long a2 = dup2(av.z);
            unsigned long long a3 = dup2(av.w);
            ffma2(acc[0][0], a0, bp.x); ffma2(acc[0][1], a0, bp.y);
            ffma2(acc[1][0], a1, bp.x); ffma2(acc[1][1], a1, bp.y);
            ffma2(acc[2][0], a2, bp.x); ffma2(acc[2][1], a2, bp.y);
            ffma2(acc[3][0], a3, bp.x); ffma2(acc[3][1], a3, bp.y);
        }
    }

    float4 b1v = *(const float4*)&b1[n0 + tx*4];
    float fc[4][4];
    #pragma unroll
    for (int bi = 0; bi < 4; ++bi) {
        float2 lo = unpack2(acc[bi][0]);
        float2 hi = unpack2(acc[bi][1]);
        fc[bi][0] = lo.x + b1v.x;
        fc[bi][1] = lo.y + b1v.y;
        fc[bi][2] = hi.x + b1v.z;
        fc[bi][3] = hi.y + b1v.w;
    }
    float* outp = &g_pre1[(size_t)t * (HID_*B_)];
    #pragma unroll
    for (int ni = 0; ni < 4; ++ni) {
        float4 c = make_float4(fc[0][ni], fc[1][ni], fc[2][ni], fc[3][ni]);
        *(float4*)&outp[(n0 + tx*4 + ni)*B_ + ty*4] = c;
    }
}

// ================= persistent recurrent kernel (byte-identical to R13 pass) ==========
// 16 warps. Warp kg owns k-rows [kg*64, kg*64+64). Lane (cp,q): cols c0..c0+3,
// batch rows m4..m4+3. h read from L2 (ldcg); weights plain [k][8] in smem.
// Conflict-free partials; distributed finalize.
__global__ void __launch_bounds__(TPB, 1) recur_kernel(
    const float* __restrict__ Wh1, const float* __restrict__ Wi2,
    const float* __restrict__ Wh2, const float* __restrict__ b2,
    const float* __restrict__ Wd,  const float* __restrict__ bd,
    float* __restrict__ out)
{
    extern __shared__ float sm[];
    float* Ws1  = sm;                 // [HID_][8]
    float* Wsi  = sm + WSZ;
    float* Ws2  = sm + 2 * WSZ;
    float* redA = sm + RED_OFF;       // 8192 floats (h1 partials)
    float* redB = sm + RED_OFF + 8192;// 8192 floats (h2 partials)

    const int tid  = threadIdx.x;
    const int c    = blockIdx.x;
    const int kg   = tid >> 5;           // warp = k-group 0..15
    const int lane = tid & 31;
    const int cp   = lane >> 4;          // col-quad 0..1
    const int q    = lane & 15;          // m-quad 0..15
    const int m4   = q * 4;
    const int c0   = c * NC + cp * 4;

    // fill plain weight slices [k][8]
    for (int k = tid; k < HID_; k += TPB) {
        #pragma unroll
        for (int hh = 0; hh < 2; ++hh) {
            int h4 = hh * 4;
            int col = c * NC + h4;
            float4 v;
            v.x = Wh1[(size_t)k * HID_ + col];     v.y = Wh1[(size_t)k * HID_ + col + 1];
            v.z = Wh1[(size_t)k * HID_ + col + 2]; v.w = Wh1[(size_t)k * HID_ + col + 3];
            *(float4*)&Ws1[k * 8 + h4] = v;
            v.x = Wi2[(size_t)k * HID_ + col];     v.y = Wi2[(size_t)k * HID_ + col + 1];
            v.z = Wi2[(size_t)k * HID_ + col + 2]; v.w = Wi2[(size_t)k * HID_ + col + 3];
            *(float4*)&Wsi[k * 8 + h4] = v;
            v.x = Wh2[(size_t)k * HID_ + col];     v.y = Wh2[(size_t)k * HID_ + col + 1];
            v.z = Wh2[(size_t)k * HID_ + col + 2]; v.w = Wh2[(size_t)k * HID_ + col + 3];
            *(float4*)&Ws2[k * 8 + h4] = v;
        }
    }
    if (tid < 128) {
        float4 z = {0,0,0,0};
        *(float4*)&g_H1[0][c * NC * B_ + tid * 4] = z;
        *(float4*)&g_H2[0][c * NC * B_ + tid * 4] = z;
    }
    // scalar b2 for h2-reducing warps (kg 4..7): col = c*NC + cp*4 + (kg-4)
    const float b2s = b2[c * NC + cp * 4 + (kg & 3)];
    grid_barrier();

    for (int p = 0; p <= S_; ++p) {
        const int pr = p & 1;
        const float* H1r = g_H1[pr] + (kg << 6) * B_ + m4;    // h1(p), warp k-slice
        const float* H2r = g_H2[pr ^ 1] + (kg << 6) * B_ + m4;

        unsigned long long a1[4][2], a2[4][2];
        #pragma unroll
        for (int ci = 0; ci < 4; ++ci) {
            a1[ci][0] = a1[ci][1] = 0ull;
            a2[ci][0] = a2[ci][1] = 0ull;
        }
        if (kg == 0 && p < S_) {         // seed a1 with pre1 (this thread's tile)
            const float* pp = &g_pre1[(size_t)p * (HID_ * B_)];
            #pragma unroll
            for (int ci = 0; ci < 4; ++ci) {
                ulonglong2 v = *(const ulonglong2*)&pp[(c0 + ci) * B_ + m4];
                a1[ci][0] = v.x; a1[ci][1] = v.y;
            }
        }

        const float* w1p = Ws1 + (kg << 6) * 8 + cp * 4;
        const float* wip = Wsi + (kg << 6) * 8 + cp * 4;
        const float* w2p = Ws2 + (kg << 6) * 8 + cp * 4;

        #pragma unroll 8
        for (int kk = 0; kk < 64; ++kk) {
            u64x2 h1 = ldcg16(H1r + kk * B_);
            u64x2 h2 = ldcg16(H2r + kk * B_);
            float4 w1 = *(const float4*)&w1p[kk * 8];
            float4 wi = *(const float4*)&wip[kk * 8];
            float4 w2 = *(const float4*)&w2p[kk * 8];
            const float w1a[4] = {w1.x, w1.y, w1.z, w1.w};
            const float wia[4] = {wi.x, wi.y, wi.z, wi.w};
            const float w2a[4] = {w2.x, w2.y, w2.z, w2.w};
            #pragma unroll
            for (int ci = 0; ci < 4; ++ci) {
                unsigned long long w1d = dup2(w1a[ci]);
                unsigned long long wid = dup2(wia[ci]);
                unsigned long long w2d = dup2(w2a[ci]);
                ffma2(a1[ci][0], h1.x, w1d);
                ffma2(a1[ci][1], h1.y, w1d);
                ffma2(a2[ci][0], h1.x, wid);
                ffma2(a2[ci][1], h1.y, wid);
                ffma2(a2[ci][0], h2.x, w2d);
                ffma2(a2[ci][1], h2.y, w2d);
            }
        }

        // partials -> smem, conflict-free layout:
        //   component j of (kg,lane): redA/redB[((j*16+kg)*32+lane)*4]
        {
            #pragma unroll
            for (int j = 0; j < 4; ++j) {
                ulonglong2 u;
                u.x = a1[j][0]; u.y = a1[j][1];
                *(ulonglong2*)&redA[((j * 16 + kg) * 32 + lane) * 4] = u;
            }
            #pragma unroll
            for (int j = 0; j < 4; ++j) {
                ulonglong2 u;
                u.x = a2[j][0]; u.y = a2[j][1];
                *(ulonglong2*)&redB[((j * 16 + kg) * 32 + lane) * 4] = u;
            }
        }
        __syncthreads();

        // distributed finalize (conflict-free reads): warp j -> h1 col j; warp 4+j -> h2.
        if (kg < 4 && p < S_) {
            const int j = kg;
            float4 f = {0, 0, 0, 0};
            #pragma unroll
            for (int g = 0; g < NW; ++g) {
                float4 v = *(const float4*)&redA[((j * 16 + g) * 32 + lane) * 4];
                f.x += v.x; f.y += v.y; f.z += v.z; f.w += v.w;
            }
            float4 o = make_float4(tanhf(f.x), tanhf(f.y), tanhf(f.z), tanhf(f.w));
            *(float4*)&g_H1[pr ^ 1][(c0 + j) * B_ + m4] = o;
        }
        if (kg >= 4 && kg < 8 && p > 0) {
            const int j = kg - 4;
            float4 f = {b2s, b2s, b2s, b2s};
            #pragma unroll
            for (int g = 0; g < NW; ++g) {
                float4 v = *(const float4*)&redB[((j * 16 + g) * 32 + lane) * 4];
                f.x += v.x; f.y += v.y; f.z += v.z; f.w += v.w;
            }
            float4 o = make_float4(tanhf(f.x), tanhf(f.y), tanhf(f.z), tanhf(f.w));
            *(float4*)&g_H2[pr][(c0 + j) * B_ + m4] = o;
        }
        grid_barrier();
    }

    // epilogue: out[b] = sigmoid(h2(512) @ Wd + bd); h2(512) at parity 0
    if (c == 0 && tid < 128) {
        const int b = tid >> 1, h = tid & 1;
        const float* H2f = g_H2[0];
        float s = 0.f;
        #pragma unroll 8
        for (int k = h * 512; k < h * 512 + 512; ++k)
            s += __ldcg(&H2f[k * B_ + b]) * Wd[k];
        s += __shfl_xor_sync(0xffffffffu, s, 1);
        if (h == 0) out[b] = 1.f / (1.f + expf(-(s + bd[0])));
    }
}

// ================= launch =================
extern "C" void kernel_launch(void* const* d_in, const int* in_sizes, int n_in,
                              void* d_out, int out_size) {
    const int*   x   = (const int*)  d_in[0];
    const float* emb = (const float*)d_in[1];
    const float* Wi1 = (const float*)d_in[2];
    const float* Wh1 = (const float*)d_in[3];
    const float* b1  = (const float*)d_in[4];
    const float* Wi2 = (const float*)d_in[5];
    const float* Wh2 = (const float*)d_in[6];
    const float* b2  = (const float*)d_in[7];
    const float* Wd  = (const float*)d_in[8];
    const float* bd  = (const float*)d_in[9];
    float* out = (float*)d_out;

    cudaFuncSetAttribute(recur_kernel,
                         cudaFuncAttributeMaxDynamicSharedMemorySize, SMEM_BYTES);

    pre_kernel<<<dim3(16, 512), 256>>>(x, emb, Wi1, b1);
    recur_kernel<<<NCTA, TPB, SMEM_BYTES>>>(Wh1, Wi2, Wh2, b2, Wd, bd, out);
}